// round 12
// baseline (speedup 1.0000x reference)
#include <cuda_runtime.h>
#include <math.h>

#define BB 4
#define LL 4096
#define DD 1024
#define NC1 128          // pass1 chunks per batch
#define LC1 (LL / NC1)   // 32 steps
#define NC3 64           // pass3 chunks per batch
#define LC3 (LL / NC3)   // 64 steps
#define LANES (DD / 2)   // 512 float2 lanes
#define TPB 128

// pass1 per-chunk local sums: BB*NC1*DD complex = 4 MB
__device__ float2 g_sum[BB * NC1 * DD];
// pass3 incoming states: BB*NC3*DD complex = 2 MB
__device__ float2 g_state[BB * NC3 * DD];

__device__ __forceinline__ float2 cmul(float2 a, float2 b) {
    return make_float2(fmaf(a.x, b.x, -a.y * b.y), fmaf(a.x, b.y, a.y * b.x));
}

__device__ __forceinline__ float2 get_phazor(const float* __restrict__ pr,
                                             const float* __restrict__ pi, int d) {
    float r = pr[d], i = pi[d];
    float mag = sqrtf(fmaf(r, r, i * i));
    float s = expf(-mag) / mag;
    return make_float2(r * s, i * s);
}

// step: S = p*S + x  (complex)
__device__ __forceinline__ void cstep(float2& S, const float2 p, const float xv) {
    float nr = fmaf(p.x, S.x, fmaf(-p.y, S.y, xv));
    float ni = fmaf(p.x, S.y, p.y * S.x);
    S.x = nr; S.y = ni;
}

// -------- pass 1 (R6 geometry): per-chunk local recurrence, batch-8 double buffer --------
__global__ void __launch_bounds__(TPB) pass1_kernel(const float* __restrict__ x,
                                                    const float* __restrict__ pr,
                                                    const float* __restrict__ pi,
                                                    int b) {
    int lane = blockIdx.x * TPB + threadIdx.x;  // 0..511
    int c = blockIdx.y;                          // 0..127
    int d0 = lane * 2;

    float2 p0 = get_phazor(pr, pi, d0);
    float2 p1 = get_phazor(pr, pi, d0 + 1);

    const float2* xp = (const float2*)x + ((size_t)b * LL + (size_t)c * LC1) * LANES + lane;

    float2 xs[2][8];
#pragma unroll
    for (int j = 0; j < 8; j++) xs[0][j] = xp[(size_t)j * LANES];

    float2 S0 = make_float2(0.f, 0.f);
    float2 S1 = make_float2(0.f, 0.f);
#pragma unroll
    for (int i = 0; i < LC1; i += 8) {
        int cur = (i >> 3) & 1;
        if (i + 8 < LC1) {
#pragma unroll
            for (int j = 0; j < 8; j++)
                xs[cur ^ 1][j] = xp[(size_t)(i + 8 + j) * LANES];
        }
#pragma unroll
        for (int j = 0; j < 8; j++) {
            cstep(S0, p0, xs[cur][j].x);
            cstep(S1, p1, xs[cur][j].y);
        }
    }
    float4 st = make_float4(S0.x, S0.y, S1.x, S1.y);
    ((float4*)g_sum)[((size_t)b * NC1 + c) * LANES + lane] = st;
}

// -------- pass 2 (R9 bridge): combine 128 sums (A=p^32); states at 64-step bounds --------
__global__ void __launch_bounds__(256) pass2_kernel(const float* __restrict__ pr,
                                                    const float* __restrict__ pi,
                                                    int b) {
    int d = blockIdx.x * blockDim.x + threadIdx.x;  // 0..1023

    float2 p = get_phazor(pr, pi, d);
    float2 A = p;
#pragma unroll
    for (int k = 0; k < 5; k++) A = cmul(A, A);      // p^32 = p^LC1

    float2 S = make_float2(0.f, 0.f);
#pragma unroll 1
    for (int cb = 0; cb < NC1; cb += 16) {
        float2 loc[16];
#pragma unroll
        for (int j = 0; j < 16; j++)
            loc[j] = g_sum[((size_t)b * NC1 + cb + j) * DD + d];
#pragma unroll
        for (int j = 0; j < 16; j++) {
            int c = cb + j;
            if ((c & 1) == 0)
                g_state[((size_t)b * NC3 + (c >> 1)) * DD + d] = S;
            float nr = fmaf(A.x, S.x, fmaf(-A.y, S.y, loc[j].x));
            float ni = fmaf(A.x, S.y, fmaf(A.y, S.x, loc[j].y));
            S.x = nr; S.y = ni;
        }
    }
}

// -------- pass 3 (R11): recompute with true incoming state, write output --------
template <bool CPLX>
__global__ void __launch_bounds__(TPB) pass3_kernel(const float* __restrict__ x,
                                                    const float* __restrict__ hr,
                                                    const float* __restrict__ hi,
                                                    const float* __restrict__ pr,
                                                    const float* __restrict__ pi,
                                                    const float* __restrict__ ir_,
                                                    const float* __restrict__ ii_,
                                                    float* __restrict__ out,
                                                    int b) {
    int lane = blockIdx.x * TPB + threadIdx.x;  // 0..511
    int c = blockIdx.y;                          // 0..63
    int d0 = lane * 2;

    float2 p0 = get_phazor(pr, pi, d0);
    float2 p1 = get_phazor(pr, pi, d0 + 1);

    // pc = p^(c*LC3 + 1) via A = p^LC3, A^c binary pow (c uniform per block)
    float2 A0 = p0, A1 = p1;
#pragma unroll
    for (int k = 0; k < 6; k++) { A0 = cmul(A0, A0); A1 = cmul(A1, A1); }
    float2 Ae0 = make_float2(1.f, 0.f), Ae1 = make_float2(1.f, 0.f);
    float2 b0 = A0, b1 = A1;
    int e = c;
    while (e) {
        if (e & 1) { Ae0 = cmul(Ae0, b0); Ae1 = cmul(Ae1, b1); }
        b0 = cmul(b0, b0); b1 = cmul(b1, b1);
        e >>= 1;
    }
    float2 pc0 = cmul(p0, Ae0);
    float2 pc1 = cmul(p1, Ae1);

    float2 h0 = make_float2(hr[(size_t)b * DD + d0], hi[(size_t)b * DD + d0]);
    float2 h1 = make_float2(hr[(size_t)b * DD + d0 + 1], hi[(size_t)b * DD + d0 + 1]);
    float2 hp0 = cmul(h0, pc0);   // hidden * p^(t+1) at t = c*LC3
    float2 hp1 = cmul(h1, pc1);
    float2 i0 = make_float2(ir_[d0], ii_[d0]);
    float2 i1 = make_float2(ir_[d0 + 1], ii_[d0 + 1]);

    float4 sld = ((const float4*)g_state)[((size_t)b * NC3 + c) * LANES + lane];
    float2 S0 = make_float2(sld.x, sld.y);
    float2 S1 = make_float2(sld.z, sld.w);

    size_t pair0 = ((size_t)b * LL + (size_t)c * LC3) * LANES + lane;
    const float2* xp = (const float2*)x + pair0;

    float2 xs[2][8];
#pragma unroll
    for (int j = 0; j < 8; j++) xs[0][j] = __ldcs(xp + (size_t)j * LANES);

#pragma unroll
    for (int i = 0; i < LC3; i += 8) {
        int cur = (i >> 3) & 1;
        if (i + 8 < LC3) {
#pragma unroll
            for (int j = 0; j < 8; j++)
                xs[cur ^ 1][j] = __ldcs(xp + (size_t)(i + 8 + j) * LANES);
        }
#pragma unroll
        for (int j = 0; j < 8; j++) {
            cstep(S0, p0, xs[cur][j].x);
            cstep(S1, p1, xs[cur][j].y);
            size_t pidx = pair0 + (size_t)(i + j) * LANES;
            if (CPLX) {
                float2 o0, o1;
                o0.x = fmaf(i0.x, S0.x, fmaf(-i0.y, S0.y, hp0.x));
                o0.y = fmaf(i0.x, S0.y, fmaf(i0.y, S0.x, hp0.y));
                o1.x = fmaf(i1.x, S1.x, fmaf(-i1.y, S1.y, hp1.x));
                o1.y = fmaf(i1.x, S1.y, fmaf(i1.y, S1.x, hp1.y));
                __stcs((float4*)out + pidx, make_float4(o0.x, o0.y, o1.x, o1.y));
            } else {
                float r0 = fmaf(i0.x, S0.x, fmaf(-i0.y, S0.y, hp0.x));
                float r1 = fmaf(i1.x, S1.x, fmaf(-i1.y, S1.y, hp1.x));
                __stcs((float2*)out + pidx, make_float2(r0, r1));
            }
            // hp *= p
            float t0r = fmaf(hp0.x, p0.x, -hp0.y * p0.y);
            float t0i = fmaf(hp0.x, p0.y, hp0.y * p0.x);
            hp0.x = t0r; hp0.y = t0i;
            float t1r = fmaf(hp1.x, p1.x, -hp1.y * p1.y);
            float t1i = fmaf(hp1.x, p1.y, hp1.y * p1.x);
            hp1.x = t1r; hp1.y = t1i;
        }
    }
}

extern "C" void kernel_launch(void* const* d_in, const int* in_sizes, int n_in,
                              void* d_out, int out_size) {
    const long long X_SZ = (long long)BB * LL * DD;  // 16,777,216
    const long long H_SZ = (long long)BB * DD;       // 4096
    const long long P_SZ = DD;                       // 1024

    int ix = -1;
    long long scale = 1;
    for (int i = 0; i < n_in; i++)
        if ((long long)in_sizes[i] == X_SZ) { ix = i; scale = 1; break; }
    if (ix < 0)
        for (int i = 0; i < n_in; i++)
            if ((long long)in_sizes[i] == X_SZ * 4) { ix = i; scale = 4; break; }

    const float *x, *hr, *hi, *pr, *pi, *ir_, *ii_;
    bool mapped = false;

    if (ix >= 0 && ix == n_in - 1 && n_in == 7) {
        // Alphabetical ordering
        hi  = (const float*)d_in[0];
        hr  = (const float*)d_in[1];
        pi  = (const float*)d_in[2];
        ii_ = (const float*)d_in[3];
        ir_ = (const float*)d_in[4];
        pr  = (const float*)d_in[5];
        x   = (const float*)d_in[6];
        mapped = true;
    } else if (ix >= 0) {
        x = (const float*)d_in[ix];
        const float* h_list[2] = {0, 0};
        const float* p_list[4] = {0, 0, 0, 0};
        int nh = 0, np = 0;
        for (int i = 0; i < n_in; i++) {
            if (i == ix) continue;
            long long s = (long long)in_sizes[i];
            if (s == H_SZ * scale && nh < 2) h_list[nh++] = (const float*)d_in[i];
            else if (s == P_SZ * scale && np < 4) p_list[np++] = (const float*)d_in[i];
        }
        if (nh == 2 && np == 4) {
            hr  = h_list[0]; hi  = h_list[1];
            pr  = p_list[0]; pi  = p_list[1];
            ir_ = p_list[2]; ii_ = p_list[3];
            mapped = true;
        }
    }
    if (!mapped) {
        x   = (const float*)d_in[0];
        hr  = (const float*)d_in[1];
        hi  = (const float*)d_in[2];
        pr  = (const float*)d_in[3];
        pi  = (const float*)d_in[4];
        ir_ = (const float*)d_in[5];
        ii_ = (const float*)d_in[6];
    }

    long long osz = (long long)out_size;
    bool cplx;
    if (osz == 2 * X_SZ || osz == 8 * X_SZ)       cplx = true;
    else if (osz == X_SZ || osz == 4 * X_SZ)      cplx = false;
    else                                          cplx = true;

    float* out = (float*)d_out;

    // ---- forked-stream batch pipeline ----
    // main stream: pass1(0..3)   (pure reads)
    // side stream: pass2(b); pass3(b) after pass1(b)  (mixed read+write)
    // The two kernels co-schedule, mixing read and write DRAM traffic.
    cudaStream_t m = 0;   // whatever stream the harness captures — legacy default
    // NOTE: the harness calls us on its capture stream via per-thread default
    // stream semantics; launches with <<<...>>> below go to that stream.
    // Fork:
    cudaStream_t s;
    cudaStreamCreateWithFlags(&s, cudaStreamNonBlocking);
    cudaEvent_t e1[BB], eDone;
    for (int b = 0; b < BB; b++) cudaEventCreateWithFlags(&e1[b], cudaEventDisableTiming);
    cudaEventCreateWithFlags(&eDone, cudaEventDisableTiming);

    dim3 grid1(LANES / TPB, NC1);   // (4, 128) = 512 blocks per batch
    dim3 grid3(LANES / TPB, NC3);   // (4, 64)  = 256 blocks per batch

    for (int b = 0; b < BB; b++) {
        pass1_kernel<<<grid1, TPB, 0, m>>>(x, pr, pi, b);
        cudaEventRecord(e1[b], m);
    }
    for (int b = 0; b < BB; b++) {
        cudaStreamWaitEvent(s, e1[b], 0);
        pass2_kernel<<<DD / 256, 256, 0, s>>>(pr, pi, b);
        if (cplx)
            pass3_kernel<true ><<<grid3, TPB, 0, s>>>(x, hr, hi, pr, pi, ir_, ii_, out, b);
        else
            pass3_kernel<false><<<grid3, TPB, 0, s>>>(x, hr, hi, pr, pi, ir_, ii_, out, b);
    }
    cudaEventRecord(eDone, s);
    cudaStreamWaitEvent(m, eDone, 0);   // join fork back into captured stream

    for (int b = 0; b < BB; b++) cudaEventDestroy(e1[b]);
    cudaEventDestroy(eDone);
    cudaStreamDestroy(s);
}

// round 13
// speedup vs baseline: 1.5637x; 1.5637x over previous
#include <cuda_runtime.h>
#include <math.h>

#define BB 4
#define LL 4096
#define DD 1024
#define NC 64            // chunks along time
#define LC (LL / NC)     // 64 steps per chunk
#define LANES (DD / 2)   // 512 float2 lanes
#define TPB 128
#define LB 4             // lane-blocks per (b, chunk)

// per (b, chunk, d) local sums (published in phase A)
__device__ float2 g_sum[BB * NC * DD];
// release flags per (b, chunk, lane-block)
__device__ int g_flag[BB * NC * LB];

__device__ __forceinline__ float2 cmul(float2 a, float2 b) {
    return make_float2(fmaf(a.x, b.x, -a.y * b.y), fmaf(a.x, b.y, a.y * b.x));
}

__device__ __forceinline__ float2 get_phazor(const float* __restrict__ pr,
                                             const float* __restrict__ pi, int d) {
    float r = pr[d], i = pi[d];
    float mag = sqrtf(fmaf(r, r, i * i));
    float s = expf(-mag) / mag;
    return make_float2(r * s, i * s);
}

// step: S = p*S + x  (complex)
__device__ __forceinline__ void cstep(float2& S, const float2 p, const float xv) {
    float nr = fmaf(p.x, S.x, fmaf(-p.y, S.y, xv));
    float ni = fmaf(p.x, S.y, p.y * S.x);
    S.x = nr; S.y = ni;
}

// -------- reset: zero flags (required every launch; graph replays reuse state) --------
__global__ void reset_kernel() {
    int i = blockIdx.x * blockDim.x + threadIdx.x;
    if (i < BB * NC * LB) g_flag[i] = 0;
}

// -------- fused scan: phase A (local sums) -> lookback -> phase B (outputs) --------
template <bool CPLX>
__global__ void __launch_bounds__(TPB) fused_kernel(const float* __restrict__ x,
                                                    const float* __restrict__ hr,
                                                    const float* __restrict__ hi,
                                                    const float* __restrict__ pr,
                                                    const float* __restrict__ pi,
                                                    const float* __restrict__ ir_,
                                                    const float* __restrict__ ii_,
                                                    float* __restrict__ out) {
    int lx = blockIdx.x;                 // lane-block 0..3
    int c  = blockIdx.y;                 // chunk 0..63 (lower c = lower bid: safe ordering)
    int b  = blockIdx.z;
    int lane = lx * TPB + threadIdx.x;   // 0..511
    int d0 = lane * 2;

    float2 p0 = get_phazor(pr, pi, d0);
    float2 p1 = get_phazor(pr, pi, d0 + 1);

    size_t pair0 = ((size_t)b * LL + (size_t)c * LC) * LANES + lane;
    const float2* xp = (const float2*)x + pair0;

    // ---- phase A: local recurrence with zero init ----
    float2 xs[2][8];
#pragma unroll
    for (int j = 0; j < 8; j++) xs[0][j] = xp[(size_t)j * LANES];

    float2 S0 = make_float2(0.f, 0.f);
    float2 S1 = make_float2(0.f, 0.f);
#pragma unroll
    for (int i = 0; i < LC; i += 8) {
        int cur = (i >> 3) & 1;
        if (i + 8 < LC) {
#pragma unroll
            for (int j = 0; j < 8; j++)
                xs[cur ^ 1][j] = xp[(size_t)(i + 8 + j) * LANES];
        }
#pragma unroll
        for (int j = 0; j < 8; j++) {
            cstep(S0, p0, xs[cur][j].x);
            cstep(S1, p1, xs[cur][j].y);
        }
    }
    ((float4*)g_sum)[((size_t)b * NC + c) * LANES + lane] =
        make_float4(S0.x, S0.y, S1.x, S1.y);
    __threadfence();
    __syncthreads();
    if (threadIdx.x == 0)
        atomicExch(&g_flag[((size_t)b * NC + c) * LB + lx], 1);

    // A = p^LC (needed for lookback fold and hidden power)
    float2 A0 = p0, A1 = p1;
#pragma unroll
    for (int k = 0; k < 6; k++) { A0 = cmul(A0, A0); A1 = cmul(A1, A1); }

    // ---- lookback: S_in = sum_{j<c} A^{c-1-j} * sum_j ----
    float2 P0 = make_float2(0.f, 0.f);
    float2 P1 = make_float2(0.f, 0.f);
    if (c > 0) {
        if (threadIdx.x == 0) {
            for (int j = 0; j < c; j++) {
                volatile int* f = &g_flag[((size_t)b * NC + j) * LB + lx];
                while (*f == 0) __nanosleep(20);
            }
            __threadfence();
        }
        __syncthreads();
        const float4* sums = (const float4*)g_sum;
        int j = 0;
        for (; j + 8 <= c; j += 8) {
            float4 ld[8];
#pragma unroll
            for (int u = 0; u < 8; u++)
                ld[u] = sums[((size_t)b * NC + j + u) * LANES + lane];
#pragma unroll
            for (int u = 0; u < 8; u++) {
                float nr0 = fmaf(A0.x, P0.x, fmaf(-A0.y, P0.y, ld[u].x));
                float ni0 = fmaf(A0.x, P0.y, fmaf(A0.y, P0.x, ld[u].y));
                P0.x = nr0; P0.y = ni0;
                float nr1 = fmaf(A1.x, P1.x, fmaf(-A1.y, P1.y, ld[u].z));
                float ni1 = fmaf(A1.x, P1.y, fmaf(A1.y, P1.x, ld[u].w));
                P1.x = nr1; P1.y = ni1;
            }
        }
        for (; j < c; j++) {
            float4 s = sums[((size_t)b * NC + j) * LANES + lane];
            float nr0 = fmaf(A0.x, P0.x, fmaf(-A0.y, P0.y, s.x));
            float ni0 = fmaf(A0.x, P0.y, fmaf(A0.y, P0.x, s.y));
            P0.x = nr0; P0.y = ni0;
            float nr1 = fmaf(A1.x, P1.x, fmaf(-A1.y, P1.y, s.z));
            float ni1 = fmaf(A1.x, P1.y, fmaf(A1.y, P1.x, s.w));
            P1.x = nr1; P1.y = ni1;
        }
    }

    // ---- hidden term setup: hp = hidden * p^(c*LC + 1) ----
    float2 Ae0 = make_float2(1.f, 0.f), Ae1 = make_float2(1.f, 0.f);
    {
        float2 b0 = A0, b1 = A1;
        int e = c;
        while (e) {
            if (e & 1) { Ae0 = cmul(Ae0, b0); Ae1 = cmul(Ae1, b1); }
            b0 = cmul(b0, b0); b1 = cmul(b1, b1);
            e >>= 1;
        }
    }
    float2 pc0 = cmul(p0, Ae0);
    float2 pc1 = cmul(p1, Ae1);
    float2 h0 = make_float2(hr[(size_t)b * DD + d0], hi[(size_t)b * DD + d0]);
    float2 h1 = make_float2(hr[(size_t)b * DD + d0 + 1], hi[(size_t)b * DD + d0 + 1]);
    float2 hp0 = cmul(h0, pc0);
    float2 hp1 = cmul(h1, pc1);
    float2 i0 = make_float2(ir_[d0], ii_[d0]);
    float2 i1 = make_float2(ir_[d0 + 1], ii_[d0 + 1]);

    // ---- phase B: re-run recurrence from true incoming state (x hits L2) ----
    S0 = P0; S1 = P1;
#pragma unroll
    for (int j = 0; j < 8; j++) xs[0][j] = __ldcs(xp + (size_t)j * LANES);

#pragma unroll
    for (int i = 0; i < LC; i += 8) {
        int cur = (i >> 3) & 1;
        if (i + 8 < LC) {
#pragma unroll
            for (int j = 0; j < 8; j++)
                xs[cur ^ 1][j] = __ldcs(xp + (size_t)(i + 8 + j) * LANES);
        }
#pragma unroll
        for (int j = 0; j < 8; j++) {
            cstep(S0, p0, xs[cur][j].x);
            cstep(S1, p1, xs[cur][j].y);
            size_t pidx = pair0 + (size_t)(i + j) * LANES;
            if (CPLX) {
                float2 o0, o1;
                o0.x = fmaf(i0.x, S0.x, fmaf(-i0.y, S0.y, hp0.x));
                o0.y = fmaf(i0.x, S0.y, fmaf(i0.y, S0.x, hp0.y));
                o1.x = fmaf(i1.x, S1.x, fmaf(-i1.y, S1.y, hp1.x));
                o1.y = fmaf(i1.x, S1.y, fmaf(i1.y, S1.x, hp1.y));
                __stcs((float4*)out + pidx, make_float4(o0.x, o0.y, o1.x, o1.y));
            } else {
                float r0 = fmaf(i0.x, S0.x, fmaf(-i0.y, S0.y, hp0.x));
                float r1 = fmaf(i1.x, S1.x, fmaf(-i1.y, S1.y, hp1.x));
                __stcs((float2*)out + pidx, make_float2(r0, r1));
            }
            float t0r = fmaf(hp0.x, p0.x, -hp0.y * p0.y);
            float t0i = fmaf(hp0.x, p0.y, hp0.y * p0.x);
            hp0.x = t0r; hp0.y = t0i;
            float t1r = fmaf(hp1.x, p1.x, -hp1.y * p1.y);
            float t1i = fmaf(hp1.x, p1.y, hp1.y * p1.x);
            hp1.x = t1r; hp1.y = t1i;
        }
    }
}

extern "C" void kernel_launch(void* const* d_in, const int* in_sizes, int n_in,
                              void* d_out, int out_size) {
    const long long X_SZ = (long long)BB * LL * DD;  // 16,777,216
    const long long H_SZ = (long long)BB * DD;       // 4096
    const long long P_SZ = DD;                       // 1024

    int ix = -1;
    long long scale = 1;
    for (int i = 0; i < n_in; i++)
        if ((long long)in_sizes[i] == X_SZ) { ix = i; scale = 1; break; }
    if (ix < 0)
        for (int i = 0; i < n_in; i++)
            if ((long long)in_sizes[i] == X_SZ * 4) { ix = i; scale = 4; break; }

    const float *x, *hr, *hi, *pr, *pi, *ir_, *ii_;
    bool mapped = false;

    if (ix >= 0 && ix == n_in - 1 && n_in == 7) {
        // Alphabetical ordering
        hi  = (const float*)d_in[0];
        hr  = (const float*)d_in[1];
        pi  = (const float*)d_in[2];
        ii_ = (const float*)d_in[3];
        ir_ = (const float*)d_in[4];
        pr  = (const float*)d_in[5];
        x   = (const float*)d_in[6];
        mapped = true;
    } else if (ix >= 0) {
        x = (const float*)d_in[ix];
        const float* h_list[2] = {0, 0};
        const float* p_list[4] = {0, 0, 0, 0};
        int nh = 0, np = 0;
        for (int i = 0; i < n_in; i++) {
            if (i == ix) continue;
            long long s = (long long)in_sizes[i];
            if (s == H_SZ * scale && nh < 2) h_list[nh++] = (const float*)d_in[i];
            else if (s == P_SZ * scale && np < 4) p_list[np++] = (const float*)d_in[i];
        }
        if (nh == 2 && np == 4) {
            hr  = h_list[0]; hi  = h_list[1];
            pr  = p_list[0]; pi  = p_list[1];
            ir_ = p_list[2]; ii_ = p_list[3];
            mapped = true;
        }
    }
    if (!mapped) {
        x   = (const float*)d_in[0];
        hr  = (const float*)d_in[1];
        hi  = (const float*)d_in[2];
        pr  = (const float*)d_in[3];
        pi  = (const float*)d_in[4];
        ir_ = (const float*)d_in[5];
        ii_ = (const float*)d_in[6];
    }

    long long osz = (long long)out_size;
    bool cplx;
    if (osz == 2 * X_SZ || osz == 8 * X_SZ)       cplx = true;
    else if (osz == X_SZ || osz == 4 * X_SZ)      cplx = false;
    else                                          cplx = true;

    float* out = (float*)d_out;

    reset_kernel<<<4, 256>>>();
    dim3 grid(LB, NC, BB);   // (4, 64, 4) = 1024 blocks, all co-resident
    if (cplx)
        fused_kernel<true ><<<grid, TPB>>>(x, hr, hi, pr, pi, ir_, ii_, out);
    else
        fused_kernel<false><<<grid, TPB>>>(x, hr, hi, pr, pi, ir_, ii_, out);
}

// round 14
// speedup vs baseline: 1.7007x; 1.0876x over previous
#include <cuda_runtime.h>
#include <math.h>

#define BB 4
#define LL 4096
#define DD 1024
#define NC1 128          // pass1 chunks
#define LC1 (LL / NC1)   // 32 steps
#define NC3 64           // pass3 chunks
#define LC3 (LL / NC3)   // 64 steps
#define LANES (DD / 2)   // 512 float2 lanes
#define TPB 128

// pass1 per-chunk local sums: BB*NC1*DD complex = 4 MB
__device__ float2 g_sum[BB * NC1 * DD];
// pass3 incoming states: BB*NC3*DD complex = 2 MB
__device__ float2 g_state[BB * NC3 * DD];

__device__ __forceinline__ float2 cmul(float2 a, float2 b) {
    return make_float2(fmaf(a.x, b.x, -a.y * b.y), fmaf(a.x, b.y, a.y * b.x));
}

__device__ __forceinline__ float2 get_phazor(const float* __restrict__ pr,
                                             const float* __restrict__ pi, int d) {
    float r = pr[d], i = pi[d];
    float mag = sqrtf(fmaf(r, r, i * i));
    float s = expf(-mag) / mag;
    return make_float2(r * s, i * s);
}

// step: S = p*S + x  (complex)
__device__ __forceinline__ void cstep(float2& S, const float2 p, const float xv) {
    float nr = fmaf(p.x, S.x, fmaf(-p.y, S.y, xv));
    float ni = fmaf(p.x, S.y, p.y * S.x);
    S.x = nr; S.y = ni;
}

// -------- pass 1 (R6 exact geometry, 14.27us measured): 2048 blocks x 128 thr --------
__global__ void __launch_bounds__(TPB) pass1_kernel(const float* __restrict__ x,
                                                    const float* __restrict__ pr,
                                                    const float* __restrict__ pi) {
    int lane = blockIdx.x * TPB + threadIdx.x;  // 0..511
    int c = blockIdx.y;                          // 0..127
    int b = blockIdx.z;
    int d0 = lane * 2;

    float2 p0 = get_phazor(pr, pi, d0);
    float2 p1 = get_phazor(pr, pi, d0 + 1);

    const float2* xp = (const float2*)x + ((size_t)b * LL + (size_t)c * LC1) * LANES + lane;

    float2 xs[2][8];
#pragma unroll
    for (int j = 0; j < 8; j++) xs[0][j] = xp[(size_t)j * LANES];

    float2 S0 = make_float2(0.f, 0.f);
    float2 S1 = make_float2(0.f, 0.f);
#pragma unroll
    for (int i = 0; i < LC1; i += 8) {
        int cur = (i >> 3) & 1;
        if (i + 8 < LC1) {
#pragma unroll
            for (int j = 0; j < 8; j++)
                xs[cur ^ 1][j] = xp[(size_t)(i + 8 + j) * LANES];
        }
#pragma unroll
        for (int j = 0; j < 8; j++) {
            cstep(S0, p0, xs[cur][j].x);
            cstep(S1, p1, xs[cur][j].y);
        }
    }
    float4 st = make_float4(S0.x, S0.y, S1.x, S1.y);
    ((float4*)g_sum)[((size_t)b * NC1 + c) * LANES + lane] = st;
}

// -------- pass 2 (R9 bridge, proven): combine 128 sums; states at 64-step bounds --------
__global__ void __launch_bounds__(256) pass2_kernel(const float* __restrict__ pr,
                                                    const float* __restrict__ pi) {
    int idx = blockIdx.x * blockDim.x + threadIdx.x; // 0..4095
    int d = idx & (DD - 1);
    int b = idx / DD;

    float2 p = get_phazor(pr, pi, d);
    float2 A = p;
#pragma unroll
    for (int k = 0; k < 5; k++) A = cmul(A, A);      // p^32 = p^LC1

    float2 S = make_float2(0.f, 0.f);
#pragma unroll 1
    for (int cb = 0; cb < NC1; cb += 16) {
        float2 loc[16];
#pragma unroll
        for (int j = 0; j < 16; j++)
            loc[j] = g_sum[((size_t)b * NC1 + cb + j) * DD + d];
#pragma unroll
        for (int j = 0; j < 16; j++) {
            int c = cb + j;
            if ((c & 1) == 0)
                g_state[((size_t)b * NC3 + (c >> 1)) * DD + d] = S;
            float nr = fmaf(A.x, S.x, fmaf(-A.y, S.y, loc[j].x));
            float ni = fmaf(A.x, S.y, fmaf(A.y, S.x, loc[j].y));
            S.x = nr; S.y = ni;
        }
    }
}

// -------- pass 3 (R11 exact): recompute from true incoming state, write output --------
template <bool CPLX>
__global__ void __launch_bounds__(TPB) pass3_kernel(const float* __restrict__ x,
                                                    const float* __restrict__ hr,
                                                    const float* __restrict__ hi,
                                                    const float* __restrict__ pr,
                                                    const float* __restrict__ pi,
                                                    const float* __restrict__ ir_,
                                                    const float* __restrict__ ii_,
                                                    float* __restrict__ out) {
    int lane = blockIdx.x * TPB + threadIdx.x;  // 0..511
    int c = blockIdx.y;                          // 0..63
    int b = blockIdx.z;
    int d0 = lane * 2;

    float2 p0 = get_phazor(pr, pi, d0);
    float2 p1 = get_phazor(pr, pi, d0 + 1);

    // pc = p^(c*LC3 + 1) via A = p^LC3, A^c binary pow (c uniform per block)
    float2 A0 = p0, A1 = p1;
#pragma unroll
    for (int k = 0; k < 6; k++) { A0 = cmul(A0, A0); A1 = cmul(A1, A1); }
    float2 Ae0 = make_float2(1.f, 0.f), Ae1 = make_float2(1.f, 0.f);
    float2 b0 = A0, b1 = A1;
    int e = c;
    while (e) {
        if (e & 1) { Ae0 = cmul(Ae0, b0); Ae1 = cmul(Ae1, b1); }
        b0 = cmul(b0, b0); b1 = cmul(b1, b1);
        e >>= 1;
    }
    float2 pc0 = cmul(p0, Ae0);
    float2 pc1 = cmul(p1, Ae1);

    float2 h0 = make_float2(hr[(size_t)b * DD + d0], hi[(size_t)b * DD + d0]);
    float2 h1 = make_float2(hr[(size_t)b * DD + d0 + 1], hi[(size_t)b * DD + d0 + 1]);
    float2 hp0 = cmul(h0, pc0);   // hidden * p^(t+1) at t = c*LC3
    float2 hp1 = cmul(h1, pc1);
    float2 i0 = make_float2(ir_[d0], ii_[d0]);
    float2 i1 = make_float2(ir_[d0 + 1], ii_[d0 + 1]);

    float4 sld = ((const float4*)g_state)[((size_t)b * NC3 + c) * LANES + lane];
    float2 S0 = make_float2(sld.x, sld.y);
    float2 S1 = make_float2(sld.z, sld.w);

    size_t pair0 = ((size_t)b * LL + (size_t)c * LC3) * LANES + lane;
    const float2* xp = (const float2*)x + pair0;

    float2 xs[2][8];
#pragma unroll
    for (int j = 0; j < 8; j++) xs[0][j] = __ldcs(xp + (size_t)j * LANES);

#pragma unroll
    for (int i = 0; i < LC3; i += 8) {
        int cur = (i >> 3) & 1;
        if (i + 8 < LC3) {
#pragma unroll
            for (int j = 0; j < 8; j++)
                xs[cur ^ 1][j] = __ldcs(xp + (size_t)(i + 8 + j) * LANES);
        }
#pragma unroll
        for (int j = 0; j < 8; j++) {
            cstep(S0, p0, xs[cur][j].x);
            cstep(S1, p1, xs[cur][j].y);
            size_t pidx = pair0 + (size_t)(i + j) * LANES;
            if (CPLX) {
                float2 o0, o1;
                o0.x = fmaf(i0.x, S0.x, fmaf(-i0.y, S0.y, hp0.x));
                o0.y = fmaf(i0.x, S0.y, fmaf(i0.y, S0.x, hp0.y));
                o1.x = fmaf(i1.x, S1.x, fmaf(-i1.y, S1.y, hp1.x));
                o1.y = fmaf(i1.x, S1.y, fmaf(i1.y, S1.x, hp1.y));
                __stcs((float4*)out + pidx, make_float4(o0.x, o0.y, o1.x, o1.y));
            } else {
                // real-only output: one vectorized 8B store for (d0, d0+1)
                float r0 = fmaf(i0.x, S0.x, fmaf(-i0.y, S0.y, hp0.x));
                float r1 = fmaf(i1.x, S1.x, fmaf(-i1.y, S1.y, hp1.x));
                __stcs((float2*)out + pidx, make_float2(r0, r1));
            }
            // hp *= p
            float t0r = fmaf(hp0.x, p0.x, -hp0.y * p0.y);
            float t0i = fmaf(hp0.x, p0.y, hp0.y * p0.x);
            hp0.x = t0r; hp0.y = t0i;
            float t1r = fmaf(hp1.x, p1.x, -hp1.y * p1.y);
            float t1i = fmaf(hp1.x, p1.y, hp1.y * p1.x);
            hp1.x = t1r; hp1.y = t1i;
        }
    }
}

extern "C" void kernel_launch(void* const* d_in, const int* in_sizes, int n_in,
                              void* d_out, int out_size) {
    const long long X_SZ = (long long)BB * LL * DD;  // 16,777,216
    const long long H_SZ = (long long)BB * DD;       // 4096
    const long long P_SZ = DD;                       // 1024

    int ix = -1;
    long long scale = 1;
    for (int i = 0; i < n_in; i++)
        if ((long long)in_sizes[i] == X_SZ) { ix = i; scale = 1; break; }
    if (ix < 0)
        for (int i = 0; i < n_in; i++)
            if ((long long)in_sizes[i] == X_SZ * 4) { ix = i; scale = 4; break; }

    const float *x, *hr, *hi, *pr, *pi, *ir_, *ii_;
    bool mapped = false;

    if (ix >= 0 && ix == n_in - 1 && n_in == 7) {
        // Alphabetical ordering
        hi  = (const float*)d_in[0];
        hr  = (const float*)d_in[1];
        pi  = (const float*)d_in[2];
        ii_ = (const float*)d_in[3];
        ir_ = (const float*)d_in[4];
        pr  = (const float*)d_in[5];
        x   = (const float*)d_in[6];
        mapped = true;
    } else if (ix >= 0) {
        x = (const float*)d_in[ix];
        const float* h_list[2] = {0, 0};
        const float* p_list[4] = {0, 0, 0, 0};
        int nh = 0, np = 0;
        for (int i = 0; i < n_in; i++) {
            if (i == ix) continue;
            long long s = (long long)in_sizes[i];
            if (s == H_SZ * scale && nh < 2) h_list[nh++] = (const float*)d_in[i];
            else if (s == P_SZ * scale && np < 4) p_list[np++] = (const float*)d_in[i];
        }
        if (nh == 2 && np == 4) {
            hr  = h_list[0]; hi  = h_list[1];
            pr  = p_list[0]; pi  = p_list[1];
            ir_ = p_list[2]; ii_ = p_list[3];
            mapped = true;
        }
    }
    if (!mapped) {
        x   = (const float*)d_in[0];
        hr  = (const float*)d_in[1];
        hi  = (const float*)d_in[2];
        pr  = (const float*)d_in[3];
        pi  = (const float*)d_in[4];
        ir_ = (const float*)d_in[5];
        ii_ = (const float*)d_in[6];
    }

    long long osz = (long long)out_size;
    bool cplx;
    if (osz == 2 * X_SZ || osz == 8 * X_SZ)       cplx = true;
    else if (osz == X_SZ || osz == 4 * X_SZ)      cplx = false;
    else                                          cplx = true;

    float* out = (float*)d_out;

    dim3 grid1(LANES / TPB, NC1, BB);  // (4, 128, 4) = 2048 blocks
    pass1_kernel<<<grid1, TPB>>>(x, pr, pi);
    pass2_kernel<<<(BB * DD) / 256, 256>>>(pr, pi);
    dim3 grid3(LANES / TPB, NC3, BB);  // (4, 64, 4) = 1024 blocks
    if (cplx)
        pass3_kernel<true ><<<grid3, TPB>>>(x, hr, hi, pr, pi, ir_, ii_, out);
    else
        pass3_kernel<false><<<grid3, TPB>>>(x, hr, hi, pr, pi, ir_, ii_, out);
}